// round 13
// baseline (speedup 1.0000x reference)
#include <cuda_runtime.h>
#include <cuda_bf16.h>
#include <math.h>

#define BB    32
#define SS    256
#define HH    1024
#define NROWS 8192
#define NBLK  128

typedef unsigned long long ull;

__device__ int    g_sorted[BB];
__device__ int    g_rev[BB];
__device__ int    g_tok[NROWS];
__device__ __nv_bfloat16 g_hiddenb[2 * BB * HH];
__device__ float  g_pre[NROWS * HH];
__device__ __nv_bfloat16 g_h1b[(size_t)NROWS * HH];
__device__ __nv_bfloat16 g_h2b[(size_t)NROWS * HH];
__device__ float  g_h2[(size_t)NROWS * HH];
__device__ float  g_pw[64 * HH];          // packed: head_w rows 0..32, tp2 rows 36..51
__device__ float  g_logits[NROWS * 64];
__device__ float  g_hl[NROWS];
__device__ float  g_ct[NROWS];
__device__ float  g_nll[NROWS];
__device__ float  g_zero[64];
__device__ unsigned g_cnt;

// packed fp32x2 FMA: d = a*b + d  (per-lane IEEE fp32)
__device__ __forceinline__ void ffma2(ull& d, ull a, ull b) {
    asm("fma.rn.f32x2 %0, %1, %2, %0;" : "+l"(d) : "l"(a), "l"(b));
}
__device__ __forceinline__ ull packdup(float x) {
    ull r;
    asm("mov.b64 %0, {%1, %1};" : "=l"(r) : "r"(__float_as_uint(x)));
    return r;
}
__device__ __forceinline__ float pairsum(ull v) {
    float2 f = *reinterpret_cast<float2*>(&v);
    return f.x + f.y;
}
// two packed bf16 -> f32x2 (bf16 to f32 is a 16-bit upshift)
__device__ __forceinline__ ull bf2_up(unsigned w) {
    ull r;
    asm("mov.b64 %0, {%1, %2};" : "=l"(r) : "r"(w << 16), "r"(w & 0xFFFF0000u));
    return r;
}

// ---------- prep: sort + token gather in ONE launch ----------
__global__ void k_preptok(const int* __restrict__ len, const int* __restrict__ inp) {
    __shared__ int s_sorted[BB];
    int tid = threadIdx.x;
    if (tid == 0) {
        g_cnt = 0;
        int idx[BB];
        for (int i = 0; i < BB; i++) idx[i] = i;
        for (int i = 1; i < BB; i++) {               // stable desc insertion sort
            int v = idx[i], lv = len[v], j = i - 1;
            while (j >= 0 && len[idx[j]] < lv) { idx[j + 1] = idx[j]; j--; }
            idx[j + 1] = v;
        }
        for (int p = 0; p < BB; p++) {
            g_sorted[p] = idx[p]; g_rev[idx[p]] = p; s_sorted[p] = idx[p];
        }
    }
    __syncthreads();
    for (int r = tid; r < NROWS; r += blockDim.x)
        g_tok[r] = inp[s_sorted[r >> 8] * SS + (r & 255)];
}

// hid = z @ l2h_w^T + b  (flat view == .view(2,B,H)), stored bf16 for the recurrence
__global__ void k_hidden(const float* __restrict__ z, const float* __restrict__ w,
                         const float* __restrict__ b) {
    int o = blockIdx.x * blockDim.x + threadIdx.x;
    if (o >= 2 * BB * HH) return;
    const float* zr = z + (o >> 11) * 256;
    const float* wr = w + (size_t)(o & 2047) * 256;
    float acc = 0.f;
#pragma unroll 8
    for (int k = 0; k < 256; k++) acc = fmaf(zr[k], wr[k], acc);
    g_hiddenb[o] = __float2bfloat16(acc + b[o & 2047]);
}

__global__ void k_pack(const float* __restrict__ head_w, const float* __restrict__ tp2) {
    int i = blockIdx.x * blockDim.x + threadIdx.x;
    if (i >= 64 * HH) return;
    int row = i >> 10, c = i & 1023;
    float v = 0.f;
    if (row < 33)                 v = head_w[row * HH + c];
    else if (row >= 36 && row < 52) v = tp2[(row - 36) * HH + c];
    g_pw[i] = v;
}

// ---------- SGEMM (f32x2): C[n][m] = A[row(n)][:K] . Bw[m][:K] + b1[m]+b2[m] ----------
__global__ void __launch_bounds__(256)
k_sgemm(const float* __restrict__ A, const float* __restrict__ Bw,
        const float* __restrict__ b1, const float* __restrict__ b2,
        float* __restrict__ C, int K, int M, int gather) {
    __shared__ __align__(16) float As[16][128];
    __shared__ __align__(16) float Bs[16][64];
    int tid = threadIdx.x, tx = tid & 15, ty = tid >> 4;
    int n0 = blockIdx.x * 128, m0 = blockIdx.y * 64;
    ull acc2[8][2];
#pragma unroll
    for (int r = 0; r < 8; r++) { acc2[r][0] = 0ull; acc2[r][1] = 0ull; }

    for (int k0 = 0; k0 < K; k0 += 16) {
#pragma unroll
        for (int i = 0; i < 2; i++) {
            int id = tid * 2 + i, r = id >> 2, kq = (id & 3) * 4;
            int grow = n0 + r;
            int arow = gather ? g_tok[grow] : grow;
            float4 v = *(const float4*)(A + (size_t)arow * K + k0 + kq);
            As[kq][r] = v.x; As[kq + 1][r] = v.y; As[kq + 2][r] = v.z; As[kq + 3][r] = v.w;
        }
        {
            int m = tid >> 2, kq = (tid & 3) * 4;
            float4 v = *(const float4*)(Bw + (size_t)(m0 + m) * K + k0 + kq);
            Bs[kq][m] = v.x; Bs[kq + 1][m] = v.y; Bs[kq + 2][m] = v.z; Bs[kq + 3][m] = v.w;
        }
        __syncthreads();
#pragma unroll
        for (int k = 0; k < 16; k++) {
            float4 a0 = *(float4*)&As[k][ty * 8];
            float4 a1 = *(float4*)&As[k][ty * 8 + 4];
            const ull* bp = (const ull*)&Bs[k][tx * 4];
            ull b01 = bp[0], b23 = bp[1];
            float a[8] = {a0.x, a0.y, a0.z, a0.w, a1.x, a1.y, a1.z, a1.w};
#pragma unroll
            for (int r = 0; r < 8; r++) {
                ull ap = packdup(a[r]);
                ffma2(acc2[r][0], ap, b01);
                ffma2(acc2[r][1], ap, b23);
            }
        }
        __syncthreads();
    }
    float bias[4];
#pragma unroll
    for (int c = 0; c < 4; c++) { int m = m0 + tx * 4 + c; bias[c] = b1[m] + b2[m]; }
#pragma unroll
    for (int r = 0; r < 8; r++) {
        int n = n0 + ty * 8 + r;
        float2 p0 = *(float2*)&acc2[r][0];
        float2 p1 = *(float2*)&acc2[r][1];
        float4 v = make_float4(p0.x + bias[0], p0.y + bias[1],
                               p1.x + bias[2], p1.y + bias[3]);
        *(float4*)(C + (size_t)n * M + m0 + tx * 4) = v;
    }
}

// ---------- grid barrier: REDG arrive + direct counter poll (monotonic epochs) ----------
__device__ __forceinline__ void gridbar_ep(unsigned ep) {
    __syncthreads();
    if (threadIdx.x == 0) {
        __threadfence();
        asm volatile("red.release.gpu.global.add.u32 [%0], 1;"
                     :: "l"(&g_cnt) : "memory");
        unsigned tgtv = ep * (unsigned)NBLK;
        unsigned v;
        do {
            asm volatile("ld.acquire.gpu.global.u32 %0, [%1];"
                         : "=r"(v) : "l"(&g_cnt) : "memory");
        } while (v < tgtv);
    }
    __syncthreads();
}

// ---------- fused 2-layer persistent RNN: 512 thr, warp = (b-quad, j-half) ----------
// 128 CTAs x 512 thr (16 warps -> 4/SMSP). Warp w: bq=w&7 (4 batch rows),
// jh=w>>3 (4 of CTA's 8 j-cols), full k, lane = k-stripe. Two sub-passes reuse
// 64 acc regs: A) W0hh.h1 -> Part0; B) W1ih.h1 + W1hh.h2 -> Part1.
// Reduce: 512 thr handle both layers' 256 outputs each. ONE barrier/step.
__global__ void __launch_bounds__(512, 1)
k_rnn_fused(const float* __restrict__ W0hh, const float* __restrict__ W1ih,
            const float* __restrict__ W1hh, const float* __restrict__ pre1,
            const float* __restrict__ b1ih, const float* __restrict__ b1hh,
            const __nv_bfloat16* __restrict__ hidb,
            __nv_bfloat16* __restrict__ h1b,
            float* __restrict__ h2f, __nv_bfloat16* __restrict__ h2b) {
    extern __shared__ float sm[];
    float* Ws0 = sm;                 // [8][1024]
    float* Wsi = sm + 8 * HH;
    float* Wsh = sm + 16 * HH;
    float* Part0 = sm + 24 * HH;     // [32][257]
    float* Part1 = Part0 + 32 * 257;
    int tid = threadIdx.x, bid = blockIdx.x;
    int w = tid >> 5, lane = tid & 31;
    int j0 = bid * 8;

    {   // load 3 W slices, coalesced float4
        const float4* s0 = (const float4*)(W0hh + (size_t)j0 * HH);
        const float4* s1 = (const float4*)(W1ih + (size_t)j0 * HH);
        const float4* s2 = (const float4*)(W1hh + (size_t)j0 * HH);
        float4* d0 = (float4*)Ws0; float4* d1 = (float4*)Wsi; float4* d2 = (float4*)Wsh;
        for (int i = tid; i < 8 * 256; i += 512) { d0[i] = s0[i]; d1[i] = s1[i]; d2[i] = s2[i]; }
    }
    __syncthreads();

    int bq = w & 7, jh = w >> 3;
    int b0 = bq * 4;                 // warp's 4 batch rows
    int jq = jh * 4;                 // warp's 4 local j cols
    int kl = lane * 4;               // lane's k offset

    // reduce-phase mapping: tid -> (layer, b2, jj2)
    int rtid = tid & 255;
    int b2 = rtid >> 3, jj2 = rtid & 7;
    int layer = tid >> 8;            // 0: h1 output, 1: h2 output
    int colR = ((jj2 >> 2) * 8 + (b2 >> 2)) * 16 + (b2 & 3) * 4 + (jj2 & 3);
    float bias1v = b1ih[j0 + jj2] + b1hh[j0 + jj2];
    const float* pre_base = pre1 + ((size_t)b2 * SS) * HH + j0 + jj2;
    __nv_bfloat16* out1b = h1b + ((size_t)b2 * SS) * HH + j0 + jj2;
    float*         out2f = h2f + ((size_t)b2 * SS) * HH + j0 + jj2;
    __nv_bfloat16* out2b = h2b + ((size_t)b2 * SS) * HH + j0 + jj2;
    const __nv_bfloat16* hid0 = hidb;
    const __nv_bfloat16* hid1 = hidb + BB * HH;

    const float* W0 = Ws0 + jq * HH;
    const float* Wi = Wsi + jq * HH;
    const float* Wh = Wsh + jq * HH;

    for (int s = 0; s <= SS; s++) {
        float pre_v = (layer == 0 && s < SS) ? __ldcg(&pre_base[(size_t)s * HH]) : 0.f;

        const __nv_bfloat16* p[4];   // h1(s-1) (or hid0 at s=0)
#pragma unroll
        for (int bl = 0; bl < 4; bl++)
            p[bl] = (s == 0) ? (hid0 + (b0 + bl) * HH + kl)
                             : (h1b + ((size_t)(b0 + bl) * SS + s - 1) * HH + kl);

        ull acc[4][4];

        // ---- pass A: acc = W0hh . h1 ----
#pragma unroll
        for (int bl = 0; bl < 4; bl++)
#pragma unroll
            for (int j = 0; j < 4; j++) acc[bl][j] = 0ull;
#pragma unroll
        for (int q = 0; q < 8; q++) {
            ull hx[4], hy[4];
#pragma unroll
            for (int bl = 0; bl < 4; bl++) {
                uint2 hv = __ldcg((const uint2*)(p[bl] + q * 128));
                hx[bl] = bf2_up(hv.x);
                hy[bl] = bf2_up(hv.y);
            }
#pragma unroll
            for (int j = 0; j < 4; j++) {
                ulonglong2 wv = *(const ulonglong2*)(W0 + j * HH + q * 128 + kl);
#pragma unroll
                for (int bl = 0; bl < 4; bl++) {
                    ffma2(acc[bl][j], hx[bl], wv.x);
                    ffma2(acc[bl][j], hy[bl], wv.y);
                }
            }
        }
#pragma unroll
        for (int bl = 0; bl < 4; bl++)
#pragma unroll
            for (int j = 0; j < 4; j++)
                Part0[lane * 257 + w * 16 + bl * 4 + j] = pairsum(acc[bl][j]);

        // ---- pass B: acc = W1ih . h1 + W1hh . h2 ----
        const __nv_bfloat16* r[4];   // h2(s-2) (or hid1 at s<=1)
#pragma unroll
        for (int bl = 0; bl < 4; bl++)
            r[bl] = (s <= 1) ? (hid1 + (b0 + bl) * HH + kl)
                             : (h2b + ((size_t)(b0 + bl) * SS + s - 2) * HH + kl);
#pragma unroll
        for (int bl = 0; bl < 4; bl++)
#pragma unroll
            for (int j = 0; j < 4; j++) acc[bl][j] = 0ull;
#pragma unroll
        for (int q = 0; q < 8; q++) {
            ull hx[4], hy[4], gx[4], gy[4];
#pragma unroll
            for (int bl = 0; bl < 4; bl++) {
                uint2 hv = __ldcg((const uint2*)(p[bl] + q * 128));
                uint2 gv = __ldcg((const uint2*)(r[bl] + q * 128));
                hx[bl] = bf2_up(hv.x); hy[bl] = bf2_up(hv.y);
                gx[bl] = bf2_up(gv.x); gy[bl] = bf2_up(gv.y);
            }
#pragma unroll
            for (int j = 0; j < 4; j++) {
                ulonglong2 wi = *(const ulonglong2*)(Wi + j * HH + q * 128 + kl);
                ulonglong2 wh = *(const ulonglong2*)(Wh + j * HH + q * 128 + kl);
#pragma unroll
                for (int bl = 0; bl < 4; bl++) {
                    ffma2(acc[bl][j], hx[bl], wi.x);
                    ffma2(acc[bl][j], hy[bl], wi.y);
                    ffma2(acc[bl][j], gx[bl], wh.x);
                    ffma2(acc[bl][j], gy[bl], wh.y);
                }
            }
        }
#pragma unroll
        for (int bl = 0; bl < 4; bl++)
#pragma unroll
            for (int j = 0; j < 4; j++)
                Part1[lane * 257 + w * 16 + bl * 4 + j] = pairsum(acc[bl][j]);
        __syncthreads();

        // ---- reduce + tanh + store (both layers in parallel) ----
        if (layer == 0) {
            if (s < SS) {
                float sum = pre_v;
#pragma unroll
                for (int l = 0; l < 32; l++) sum += Part0[l * 257 + colR];
                out1b[(size_t)s * HH] = __float2bfloat16(tanhf(sum));
            }
        } else {
            if (s >= 1) {
                float sum = bias1v;
#pragma unroll
                for (int l = 0; l < 32; l++) sum += Part1[l * 257 + colR];
                float hv = tanhf(sum);
                __stcg(&out2f[(size_t)(s - 1) * HH], hv);
                out2b[(size_t)(s - 1) * HH] = __float2bfloat16(hv);
            }
        }
        gridbar_ep((unsigned)(s + 1));
    }
}

// ---------- head logsumexp (33 logits) ----------
__global__ void k_head() {
    int r = blockIdx.x * blockDim.x + threadIdx.x;
    if (r >= NROWS) return;
    int rr = g_rev[r >> 8] * 256 + (r & 255);
    const float* L = g_logits + (size_t)rr * 64;
    float m = -1e30f;
    for (int j = 0; j < 33; j++) m = fmaxf(m, L[j]);
    float se = 0.f;
    for (int j = 0; j < 33; j++) se += __expf(L[j] - m);
    g_hl[r] = m + logf(se);
}

// ---------- tail cluster 2 (19000 words x 16): warp=word-stripe, lane=row ----------
__global__ void __launch_bounds__(128)
k_tail2(const float* __restrict__ tw2, const int* __restrict__ target) {
    __shared__ float s_tl[32], s_m[4][32], s_s[4][32];
    int tid = threadIdx.x, warp = tid >> 5, lane = tid & 31;
    int r = blockIdx.x * 32 + lane;
    int tgt = target[r];
    int rr = g_rev[r >> 8] * 256 + (r & 255);
    const ulonglong2* pr = (const ulonglong2*)&g_logits[(size_t)rr * 64 + 36];
    ulonglong2 p0 = pr[0], p1 = pr[1], p2 = pr[2], p3 = pr[3];
    int wt = tgt - 1000;
    float m = -1e30f, se = 0.f;
    for (int w = warp; w < 19000; w += 4) {
        const ulonglong2* wr = (const ulonglong2*)(tw2 + (size_t)w * 16);
        ulonglong2 q0 = wr[0], q1 = wr[1], q2 = wr[2], q3 = wr[3];
        ull a = 0ull;
        ffma2(a, p0.x, q0.x); ffma2(a, p0.y, q0.y);
        ffma2(a, p1.x, q1.x); ffma2(a, p1.y, q1.y);
        ffma2(a, p2.x, q2.x); ffma2(a, p2.y, q2.y);
        ffma2(a, p3.x, q3.x); ffma2(a, p3.y, q3.y);
        float l = pairsum(a);
        if (w == wt) s_tl[lane] = l;
        if (l > m) { se = se * __expf(m - l) + 1.f; m = l; }
        else       se += __expf(l - m);
    }
    s_m[warp][lane] = m; s_s[warp][lane] = se;
    __syncthreads();
    if (warp == 0) {
        float M = s_m[0][lane];
        for (int q = 1; q < 4; q++) M = fmaxf(M, s_m[q][lane]);
        float S = 0.f;
        for (int q = 0; q < 4; q++) S += s_s[q][lane] * __expf(s_m[q][lane] - M);
        if (tgt >= 1000) g_ct[r] = (M + logf(S)) - s_tl[lane];
    }
}

// ---------- tail clusters 0/1 (rare rows), early exit ----------
__global__ void __launch_bounds__(128)
k_tail01(const float* __restrict__ tp0, const float* __restrict__ tw0,
         const float* __restrict__ tp1, const float* __restrict__ tw1,
         const int* __restrict__ target) {
    int r = blockIdx.x;
    int tgt = target[r];
    if (tgt < 30 || tgt >= 1000) return;
    int lo, nw, d; const float *P, *W;
    if (tgt < 100) { lo = 30; nw = 70; d = 256; P = tp0; W = tw0; }
    else           { lo = 100; nw = 900; d = 64; P = tp1; W = tw1; }
    int tid = threadIdx.x, lane = tid & 31, warp = tid >> 5;
    int rr = g_rev[r >> 8] * 256 + (r & 255);
    __shared__ float xs[HH], proj[256], rm[128], rs[128], s_tl;
    const float* xr = g_h2 + (size_t)rr * HH;
    for (int i = tid; i < HH; i += 128) xs[i] = xr[i];
    __syncthreads();
    for (int p = warp; p < d; p += 4) {
        const float* wr = P + (size_t)p * HH;
        float s = 0.f;
        for (int k = lane; k < HH; k += 32) s = fmaf(xs[k], wr[k], s);
#pragma unroll
        for (int off = 16; off; off >>= 1) s += __shfl_xor_sync(0xffffffffu, s, off);
        if (lane == 0) proj[p] = s;
    }
    __syncthreads();
    float m = -1e30f, se = 0.f;
    for (int w = tid; w < nw; w += 128) {
        const float* wr = W + (size_t)w * d;
        float l = 0.f;
        for (int k = 0; k < d; k++) l = fmaf(proj[k], wr[k], l);
        if (w == tgt - lo) s_tl = l;
        if (l > m) { se = se * __expf(m - l) + 1.f; m = l; }
        else       se += __expf(l - m);
    }
    rm[tid] = m; rs[tid] = se;
    __syncthreads();
    if (tid == 0) {
        float M = -1e30f;
        for (int i = 0; i < 128; i++) M = fmaxf(M, rm[i]);
        float S = 0.f;
        for (int i = 0; i < 128; i++) S += rs[i] * __expf(rm[i] - M);
        g_ct[r] = (M + logf(S)) - s_tl;
    }
}

// ---------- assemble + deterministic sum ----------
__global__ void k_final(const int* __restrict__ target) {
    int r = blockIdx.x * blockDim.x + threadIdx.x;
    if (r >= NROWS) return;
    int tgt = target[r];
    int rr = g_rev[r >> 8] * 256 + (r & 255);
    float nll;
    if (tgt == 0) nll = 0.f;
    else if (tgt < 30) nll = g_hl[r] - g_logits[(size_t)rr * 64 + tgt];
    else {
        int ci = tgt < 100 ? 0 : (tgt < 1000 ? 1 : 2);
        nll = (g_hl[r] - g_logits[(size_t)rr * 64 + 30 + ci]) + g_ct[r];
    }
    g_nll[r] = nll;
}

__global__ void k_sum(float* __restrict__ out) {
    __shared__ float sd[256];
    int tid = threadIdx.x;
    float s = 0.f;
    for (int i = tid; i < NROWS; i += 256) s += g_nll[i];
    sd[tid] = s;
    __syncthreads();
    for (int st = 128; st; st >>= 1) {
        if (tid < st) sd[tid] += sd[tid + st];
        __syncthreads();
    }
    if (tid == 0) out[0] = sd[0];
}

#define RNN_SMEM ((24 * HH + 2 * 32 * 257) * 4)

extern "C" void kernel_launch(void* const* d_in, const int* in_sizes, int n_in,
                              void* d_out, int out_size) {
    const float* z      = (const float*)d_in[0];
    const float* emb    = (const float*)d_in[1];
    const float* l2h_w  = (const float*)d_in[2];
    const float* l2h_b  = (const float*)d_in[3];
    const float* r0wih  = (const float*)d_in[4];
    const float* r0whh  = (const float*)d_in[5];
    const float* r0bih  = (const float*)d_in[6];
    const float* r0bhh  = (const float*)d_in[7];
    const float* r1wih  = (const float*)d_in[8];
    const float* r1whh  = (const float*)d_in[9];
    const float* r1bih  = (const float*)d_in[10];
    const float* r1bhh  = (const float*)d_in[11];
    const float* head_w = (const float*)d_in[12];
    const float* tp0    = (const float*)d_in[13];
    const float* tw0    = (const float*)d_in[14];
    const float* tp1    = (const float*)d_in[15];
    const float* tw1    = (const float*)d_in[16];
    const float* tp2    = (const float*)d_in[17];
    const float* tw2    = (const float*)d_in[18];
    const int*   inp    = (const int*)d_in[19];
    const int*   target = (const int*)d_in[20];
    const int*   length = (const int*)d_in[21];
    float* out = (float*)d_out;

    __nv_bfloat16* gh1b = nullptr; __nv_bfloat16* gh2b = nullptr;
    __nv_bfloat16* ghidb = nullptr;
    float* gh2 = nullptr; float* gz = nullptr; float* gpw = nullptr;
    float* gpre = nullptr; float* glog = nullptr;
    cudaGetSymbolAddress((void**)&gh1b, g_h1b);
    cudaGetSymbolAddress((void**)&gh2b, g_h2b);
    cudaGetSymbolAddress((void**)&gh2, g_h2);
    cudaGetSymbolAddress((void**)&gz, g_zero);
    cudaGetSymbolAddress((void**)&gpw, g_pw);
    cudaGetSymbolAddress((void**)&ghidb, g_hiddenb);
    cudaGetSymbolAddress((void**)&gpre, g_pre);
    cudaGetSymbolAddress((void**)&glog, g_logits);

    cudaFuncSetAttribute(k_rnn_fused, cudaFuncAttributeMaxDynamicSharedMemorySize, RNN_SMEM);

    k_preptok<<<1, 256>>>(length, inp);
    k_hidden<<<(2 * BB * HH) / 256, 256>>>(z, l2h_w, l2h_b);

    // layer 0 input pre-activations: emb[tok] @ W0ih^T + b0ih + b0hh
    k_sgemm<<<dim3(64, 16), 256>>>(emb, r0wih, r0bih, r0bhh, gpre, 512, HH, 1);
    // fused 2-layer recurrence (512 thr, 2 sub-passes, 4 warps/SMSP)
    k_rnn_fused<<<NBLK, 512, RNN_SMEM>>>(r0whh, r1wih, r1whh, gpre,
                                         r1bih, r1bhh, ghidb, gh1b, gh2, gh2b);

    k_pack<<<64 * HH / 256, 256>>>(head_w, tp2);
    // packed head + tail2-proj logits: [8192 x 64]
    k_sgemm<<<dim3(64, 1), 256>>>(gh2, gpw, gz, gz, glog, HH, 64, 0);

    k_head<<<NROWS / 256, 256>>>();
    k_tail2<<<NROWS / 32, 128>>>(tw2, target);
    k_tail01<<<NROWS, 128>>>(tp0, tw0, tp1, tw1, target);
    k_final<<<NROWS / 256, 256>>>(target);
    k_sum<<<1, 256>>>(out);
    (void)in_sizes; (void)n_in; (void)out_size;
}

// round 14
// speedup vs baseline: 1.5215x; 1.5215x over previous
#include <cuda_runtime.h>
#include <cuda_bf16.h>
#include <math.h>

#define BB    32
#define SS    256
#define HH    1024
#define NROWS 8192
#define NBLK  128

typedef unsigned long long ull;

__device__ int    g_sorted[BB];
__device__ int    g_rev[BB];
__device__ int    g_tok[NROWS];
__device__ __nv_bfloat16 g_hiddenb[2 * BB * HH];
__device__ float  g_pre[NROWS * HH];
__device__ __nv_bfloat16 g_h1b[(size_t)NROWS * HH];
__device__ __nv_bfloat16 g_h2b[(size_t)NROWS * HH];
__device__ float  g_h2[(size_t)NROWS * HH];
__device__ float  g_pw[64 * HH];          // packed: head_w rows 0..32, tp2 rows 36..51
__device__ float  g_logits[NROWS * 64];
__device__ float  g_hl[NROWS];
__device__ float  g_ct[NROWS];
__device__ float  g_nll[NROWS];
__device__ float  g_zero[64];
__device__ unsigned g_cnt;

// packed fp32x2 FMA: d = a*b + d  (per-lane IEEE fp32)
__device__ __forceinline__ void ffma2(ull& d, ull a, ull b) {
    asm("fma.rn.f32x2 %0, %1, %2, %0;" : "+l"(d) : "l"(a), "l"(b));
}
__device__ __forceinline__ ull packdup(float x) {
    ull r;
    asm("mov.b64 %0, {%1, %1};" : "=l"(r) : "r"(__float_as_uint(x)));
    return r;
}
__device__ __forceinline__ float pairsum(ull v) {
    float2 f = *reinterpret_cast<float2*>(&v);
    return f.x + f.y;
}
// two packed bf16 -> f32x2 (bf16 to f32 is a 16-bit upshift)
__device__ __forceinline__ ull bf2_up(unsigned w) {
    ull r;
    asm("mov.b64 %0, {%1, %2};" : "=l"(r) : "r"(w << 16), "r"(w & 0xFFFF0000u));
    return r;
}

// in-warp butterfly reduce-scatter: lane l ends with sum over all 32 lanes of v[l]
__device__ __forceinline__ float warp_reduce_scatter32(float* v, int lane) {
#pragma unroll
    for (int off = 16; off; off >>= 1) {
#pragma unroll
        for (int i = 0; i < off; i++) {
            float a = v[i], b = v[i + off];
            float send = (lane & off) ? a : b;
            float recv = __shfl_xor_sync(0xffffffffu, send, off);
            v[i] = ((lane & off) ? b : a) + recv;
        }
    }
    return v[0];
}

// ---------- prep: sort + token gather in ONE launch ----------
__global__ void k_preptok(const int* __restrict__ len, const int* __restrict__ inp) {
    __shared__ int s_sorted[BB];
    int tid = threadIdx.x;
    if (tid == 0) {
        g_cnt = 0;
        int idx[BB];
        for (int i = 0; i < BB; i++) idx[i] = i;
        for (int i = 1; i < BB; i++) {               // stable desc insertion sort
            int v = idx[i], lv = len[v], j = i - 1;
            while (j >= 0 && len[idx[j]] < lv) { idx[j + 1] = idx[j]; j--; }
            idx[j + 1] = v;
        }
        for (int p = 0; p < BB; p++) {
            g_sorted[p] = idx[p]; g_rev[idx[p]] = p; s_sorted[p] = idx[p];
        }
    }
    __syncthreads();
    for (int r = tid; r < NROWS; r += blockDim.x)
        g_tok[r] = inp[s_sorted[r >> 8] * SS + (r & 255)];
}

// hid = z @ l2h_w^T + b  (flat view == .view(2,B,H)), stored bf16 for the recurrence
__global__ void k_hidden(const float* __restrict__ z, const float* __restrict__ w,
                         const float* __restrict__ b) {
    int o = blockIdx.x * blockDim.x + threadIdx.x;
    if (o >= 2 * BB * HH) return;
    const float* zr = z + (o >> 11) * 256;
    const float* wr = w + (size_t)(o & 2047) * 256;
    float acc = 0.f;
#pragma unroll 8
    for (int k = 0; k < 256; k++) acc = fmaf(zr[k], wr[k], acc);
    g_hiddenb[o] = __float2bfloat16(acc + b[o & 2047]);
}

__global__ void k_pack(const float* __restrict__ head_w, const float* __restrict__ tp2) {
    int i = blockIdx.x * blockDim.x + threadIdx.x;
    if (i >= 64 * HH) return;
    int row = i >> 10, c = i & 1023;
    float v = 0.f;
    if (row < 33)                 v = head_w[row * HH + c];
    else if (row >= 36 && row < 52) v = tp2[(row - 36) * HH + c];
    g_pw[i] = v;
}

// ---------- SGEMM (f32x2): C[n][m] = A[row(n)][:K] . Bw[m][:K] + b1[m]+b2[m] ----------
__global__ void __launch_bounds__(256)
k_sgemm(const float* __restrict__ A, const float* __restrict__ Bw,
        const float* __restrict__ b1, const float* __restrict__ b2,
        float* __restrict__ C, int K, int M, int gather) {
    __shared__ __align__(16) float As[16][128];
    __shared__ __align__(16) float Bs[16][64];
    int tid = threadIdx.x, tx = tid & 15, ty = tid >> 4;
    int n0 = blockIdx.x * 128, m0 = blockIdx.y * 64;
    ull acc2[8][2];
#pragma unroll
    for (int r = 0; r < 8; r++) { acc2[r][0] = 0ull; acc2[r][1] = 0ull; }

    for (int k0 = 0; k0 < K; k0 += 16) {
#pragma unroll
        for (int i = 0; i < 2; i++) {
            int id = tid * 2 + i, r = id >> 2, kq = (id & 3) * 4;
            int grow = n0 + r;
            int arow = gather ? g_tok[grow] : grow;
            float4 v = *(const float4*)(A + (size_t)arow * K + k0 + kq);
            As[kq][r] = v.x; As[kq + 1][r] = v.y; As[kq + 2][r] = v.z; As[kq + 3][r] = v.w;
        }
        {
            int m = tid >> 2, kq = (tid & 3) * 4;
            float4 v = *(const float4*)(Bw + (size_t)(m0 + m) * K + k0 + kq);
            Bs[kq][m] = v.x; Bs[kq + 1][m] = v.y; Bs[kq + 2][m] = v.z; Bs[kq + 3][m] = v.w;
        }
        __syncthreads();
#pragma unroll
        for (int k = 0; k < 16; k++) {
            float4 a0 = *(float4*)&As[k][ty * 8];
            float4 a1 = *(float4*)&As[k][ty * 8 + 4];
            const ull* bp = (const ull*)&Bs[k][tx * 4];
            ull b01 = bp[0], b23 = bp[1];
            float a[8] = {a0.x, a0.y, a0.z, a0.w, a1.x, a1.y, a1.z, a1.w};
#pragma unroll
            for (int r = 0; r < 8; r++) {
                ull ap = packdup(a[r]);
                ffma2(acc2[r][0], ap, b01);
                ffma2(acc2[r][1], ap, b23);
            }
        }
        __syncthreads();
    }
    float bias[4];
#pragma unroll
    for (int c = 0; c < 4; c++) { int m = m0 + tx * 4 + c; bias[c] = b1[m] + b2[m]; }
#pragma unroll
    for (int r = 0; r < 8; r++) {
        int n = n0 + ty * 8 + r;
        float2 p0 = *(float2*)&acc2[r][0];
        float2 p1 = *(float2*)&acc2[r][1];
        float4 v = make_float4(p0.x + bias[0], p0.y + bias[1],
                               p1.x + bias[2], p1.y + bias[3]);
        *(float4*)(C + (size_t)n * M + m0 + tx * 4) = v;
    }
}

// ---------- grid barrier: REDG arrive + direct counter poll (monotonic epochs) ----------
__device__ __forceinline__ void gridbar_ep(unsigned ep) {
    __syncthreads();
    if (threadIdx.x == 0) {
        __threadfence();
        asm volatile("red.release.gpu.global.add.u32 [%0], 1;"
                     :: "l"(&g_cnt) : "memory");
        unsigned tgtv = ep * (unsigned)NBLK;
        unsigned v;
        do {
            asm volatile("ld.acquire.gpu.global.u32 %0, [%1];"
                         : "=r"(v) : "l"(&g_cnt) : "memory");
        } while (v < tgtv);
    }
    __syncthreads();
}

// ---------- fused 2-layer persistent RNN, bf16 state, warp-local butterfly reduce ----------
// 128 CTAs x 256 thr; CTA owns j0..j0+7 of BOTH layers. Warp w owns batch rows
// 4w..4w+3 over full k (lane = k-stripe) -> its 32 outputs (4b x 8j) are fully
// reducible IN-WARP via shfl butterfly (no Part smem, no intra-step syncthreads).
// h1/h2 stored bf16; h2 also fp32 for softmax. ONE grid barrier/step (257).
__global__ void __launch_bounds__(256, 1)
k_rnn_fused(const float* __restrict__ W0hh, const float* __restrict__ W1ih,
            const float* __restrict__ W1hh, const float* __restrict__ pre1,
            const float* __restrict__ b1ih, const float* __restrict__ b1hh,
            const __nv_bfloat16* __restrict__ hidb,
            __nv_bfloat16* __restrict__ h1b,
            float* __restrict__ h2f, __nv_bfloat16* __restrict__ h2b) {
    extern __shared__ float sm[];
    float* Ws0 = sm;                 // [8][1024]
    float* Wsi = sm + 8 * HH;
    float* Wsh = sm + 16 * HH;
    int tid = threadIdx.x, bid = blockIdx.x;
    int w = tid >> 5, lane = tid & 31;
    int j0 = bid * 8;

    {   // load 3 W slices, coalesced float4
        const float4* s0 = (const float4*)(W0hh + (size_t)j0 * HH);
        const float4* s1 = (const float4*)(W1ih + (size_t)j0 * HH);
        const float4* s2 = (const float4*)(W1hh + (size_t)j0 * HH);
        float4* d0 = (float4*)Ws0; float4* d1 = (float4*)Wsi; float4* d2 = (float4*)Wsh;
        for (int i = tid; i < 8 * 256; i += 256) { d0[i] = s0[i]; d1[i] = s1[i]; d2[i] = s2[i]; }
    }
    __syncthreads();

    int b0 = w * 4;              // warp's 4 batch rows
    int kl = lane * 4;           // lane's k offset
    // output coords for THIS lane after butterfly reduce: out index l -> (bl=l>>3, j=l&7)
    int ob = b0 + (lane >> 3);
    int oj = j0 + (lane & 7);
    float bias1v = b1ih[oj] + b1hh[oj];
    const float* pre_base = pre1 + ((size_t)ob * SS) * HH + oj;
    __nv_bfloat16* out1b = h1b + ((size_t)ob * SS) * HH + oj;
    float*         out2f = h2f + ((size_t)ob * SS) * HH + oj;
    __nv_bfloat16* out2b = h2b + ((size_t)ob * SS) * HH + oj;
    const __nv_bfloat16* hid0 = hidb;
    const __nv_bfloat16* hid1 = hidb + BB * HH;

    for (int s = 0; s <= SS; s++) {
        float pre_v = (s < SS) ? __ldcg(&pre_base[(size_t)s * HH]) : 0.f;

        const __nv_bfloat16* p[4];   // h1(s-1) (or hid0 at s=0)
        const __nv_bfloat16* r[4];   // h2(s-2) (or hid1 at s<=1)
#pragma unroll
        for (int bl = 0; bl < 4; bl++) {
            p[bl] = (s == 0) ? (hid0 + (b0 + bl) * HH + kl)
                             : (h1b + ((size_t)(b0 + bl) * SS + s - 1) * HH + kl);
            r[bl] = (s <= 1) ? (hid1 + (b0 + bl) * HH + kl)
                             : (h2b + ((size_t)(b0 + bl) * SS + s - 2) * HH + kl);
        }

        ull acc0[4][8], accI[4][8];
#pragma unroll
        for (int bl = 0; bl < 4; bl++)
#pragma unroll
            for (int j = 0; j < 8; j++) { acc0[bl][j] = 0ull; accI[bl][j] = 0ull; }

        // combined pass: h1 shared by W0hh and W1ih
#pragma unroll
        for (int q = 0; q < 8; q++) {
            ull hx[4], hy[4];
#pragma unroll
            for (int bl = 0; bl < 4; bl++) {
                uint2 hv = __ldcg((const uint2*)(p[bl] + q * 128));
                hx[bl] = bf2_up(hv.x);
                hy[bl] = bf2_up(hv.y);
            }
#pragma unroll
            for (int j = 0; j < 8; j++) {
                ulonglong2 w0 = *(const ulonglong2*)(Ws0 + j * HH + q * 128 + kl);
                ulonglong2 wi = *(const ulonglong2*)(Wsi + j * HH + q * 128 + kl);
#pragma unroll
                for (int bl = 0; bl < 4; bl++) {
                    ffma2(acc0[bl][j], hx[bl], w0.x);
                    ffma2(acc0[bl][j], hy[bl], w0.y);
                    ffma2(accI[bl][j], hx[bl], wi.x);
                    ffma2(accI[bl][j], hy[bl], wi.y);
                }
            }
        }
        // W1hh pass: h2(s-2), accumulate into accI
#pragma unroll
        for (int q = 0; q < 8; q++) {
            ull hx[4], hy[4];
#pragma unroll
            for (int bl = 0; bl < 4; bl++) {
                uint2 hv = __ldcg((const uint2*)(r[bl] + q * 128));
                hx[bl] = bf2_up(hv.x);
                hy[bl] = bf2_up(hv.y);
            }
#pragma unroll
            for (int j = 0; j < 8; j++) {
                ulonglong2 wh = *(const ulonglong2*)(Wsh + j * HH + q * 128 + kl);
#pragma unroll
                for (int bl = 0; bl < 4; bl++) {
                    ffma2(accI[bl][j], hx[bl], wh.x);
                    ffma2(accI[bl][j], hy[bl], wh.y);
                }
            }
        }

        // ---- in-warp butterfly reduce (sequenced to limit reg pressure) ----
        float o0, o1;
        {
            float v0[32];
#pragma unroll
            for (int bl = 0; bl < 4; bl++)
#pragma unroll
                for (int j = 0; j < 8; j++) v0[bl * 8 + j] = pairsum(acc0[bl][j]);
            o0 = warp_reduce_scatter32(v0, lane);
        }
        {
            float v1[32];
#pragma unroll
            for (int bl = 0; bl < 4; bl++)
#pragma unroll
                for (int j = 0; j < 8; j++) v1[bl * 8 + j] = pairsum(accI[bl][j]);
            o1 = warp_reduce_scatter32(v1, lane);
        }

        if (s < SS)
            out1b[(size_t)s * HH] = __float2bfloat16(tanhf(pre_v + o0));
        if (s >= 1) {
            float hv = tanhf(bias1v + o1);
            __stcg(&out2f[(size_t)(s - 1) * HH], hv);
            out2b[(size_t)(s - 1) * HH] = __float2bfloat16(hv);
        }
        gridbar_ep((unsigned)(s + 1));
    }
}

// ---------- head logsumexp (33 logits) ----------
__global__ void k_head() {
    int r = blockIdx.x * blockDim.x + threadIdx.x;
    if (r >= NROWS) return;
    int rr = g_rev[r >> 8] * 256 + (r & 255);
    const float* L = g_logits + (size_t)rr * 64;
    float m = -1e30f;
    for (int j = 0; j < 33; j++) m = fmaxf(m, L[j]);
    float se = 0.f;
    for (int j = 0; j < 33; j++) se += __expf(L[j] - m);
    g_hl[r] = m + logf(se);
}

// ---------- tail cluster 2 (19000 words x 16): warp=word-stripe, lane=row ----------
__global__ void __launch_bounds__(128)
k_tail2(const float* __restrict__ tw2, const int* __restrict__ target) {
    __shared__ float s_tl[32], s_m[4][32], s_s[4][32];
    int tid = threadIdx.x, warp = tid >> 5, lane = tid & 31;
    int r = blockIdx.x * 32 + lane;
    int tgt = target[r];
    int rr = g_rev[r >> 8] * 256 + (r & 255);
    const ulonglong2* pr = (const ulonglong2*)&g_logits[(size_t)rr * 64 + 36];
    ulonglong2 p0 = pr[0], p1 = pr[1], p2 = pr[2], p3 = pr[3];
    int wt = tgt - 1000;
    float m = -1e30f, se = 0.f;
    for (int w = warp; w < 19000; w += 4) {
        const ulonglong2* wr = (const ulonglong2*)(tw2 + (size_t)w * 16);
        ulonglong2 q0 = wr[0], q1 = wr[1], q2 = wr[2], q3 = wr[3];
        ull a = 0ull;
        ffma2(a, p0.x, q0.x); ffma2(a, p0.y, q0.y);
        ffma2(a, p1.x, q1.x); ffma2(a, p1.y, q1.y);
        ffma2(a, p2.x, q2.x); ffma2(a, p2.y, q2.y);
        ffma2(a, p3.x, q3.x); ffma2(a, p3.y, q3.y);
        float l = pairsum(a);
        if (w == wt) s_tl[lane] = l;
        if (l > m) { se = se * __expf(m - l) + 1.f; m = l; }
        else       se += __expf(l - m);
    }
    s_m[warp][lane] = m; s_s[warp][lane] = se;
    __syncthreads();
    if (warp == 0) {
        float M = s_m[0][lane];
        for (int q = 1; q < 4; q++) M = fmaxf(M, s_m[q][lane]);
        float S = 0.f;
        for (int q = 0; q < 4; q++) S += s_s[q][lane] * __expf(s_m[q][lane] - M);
        if (tgt >= 1000) g_ct[r] = (M + logf(S)) - s_tl[lane];
    }
}

// ---------- tail clusters 0/1 (rare rows), early exit ----------
__global__ void __launch_bounds__(128)
k_tail01(const float* __restrict__ tp0, const float* __restrict__ tw0,
         const float* __restrict__ tp1, const float* __restrict__ tw1,
         const int* __restrict__ target) {
    int r = blockIdx.x;
    int tgt = target[r];
    if (tgt < 30 || tgt >= 1000) return;
    int lo, nw, d; const float *P, *W;
    if (tgt < 100) { lo = 30; nw = 70; d = 256; P = tp0; W = tw0; }
    else           { lo = 100; nw = 900; d = 64; P = tp1; W = tw1; }
    int tid = threadIdx.x, lane = tid & 31, warp = tid >> 5;
    int rr = g_rev[r >> 8] * 256 + (r & 255);
    __shared__ float xs[HH], proj[256], rm[128], rs[128], s_tl;
    const float* xr = g_h2 + (size_t)rr * HH;
    for (int i = tid; i < HH; i += 128) xs[i] = xr[i];
    __syncthreads();
    for (int p = warp; p < d; p += 4) {
        const float* wr = P + (size_t)p * HH;
        float s = 0.f;
        for (int k = lane; k < HH; k += 32) s = fmaf(xs[k], wr[k], s);
#pragma unroll
        for (int off = 16; off; off >>= 1) s += __shfl_xor_sync(0xffffffffu, s, off);
        if (lane == 0) proj[p] = s;
    }
    __syncthreads();
    float m = -1e30f, se = 0.f;
    for (int w = tid; w < nw; w += 128) {
        const float* wr = W + (size_t)w * d;
        float l = 0.f;
        for (int k = 0; k < d; k++) l = fmaf(proj[k], wr[k], l);
        if (w == tgt - lo) s_tl = l;
        if (l > m) { se = se * __expf(m - l) + 1.f; m = l; }
        else       se += __expf(l - m);
    }
    rm[tid] = m; rs[tid] = se;
    __syncthreads();
    if (tid == 0) {
        float M = -1e30f;
        for (int i = 0; i < 128; i++) M = fmaxf(M, rm[i]);
        float S = 0.f;
        for (int i = 0; i < 128; i++) S += rs[i] * __expf(rm[i] - M);
        g_ct[r] = (M + logf(S)) - s_tl;
    }
}

// ---------- assemble + deterministic sum ----------
__global__ void k_final(const int* __restrict__ target) {
    int r = blockIdx.x * blockDim.x + threadIdx.x;
    if (r >= NROWS) return;
    int tgt = target[r];
    int rr = g_rev[r >> 8] * 256 + (r & 255);
    float nll;
    if (tgt == 0) nll = 0.f;
    else if (tgt < 30) nll = g_hl[r] - g_logits[(size_t)rr * 64 + tgt];
    else {
        int ci = tgt < 100 ? 0 : (tgt < 1000 ? 1 : 2);
        nll = (g_hl[r] - g_logits[(size_t)rr * 64 + 30 + ci]) + g_ct[r];
    }
    g_nll[r] = nll;
}

__global__ void k_sum(float* __restrict__ out) {
    __shared__ float sd[256];
    int tid = threadIdx.x;
    float s = 0.f;
    for (int i = tid; i < NROWS; i += 256) s += g_nll[i];
    sd[tid] = s;
    __syncthreads();
    for (int st = 128; st; st >>= 1) {
        if (tid < st) sd[tid] += sd[tid + st];
        __syncthreads();
    }
    if (tid == 0) out[0] = sd[0];
}

#define RNN_SMEM (24 * HH * 4)

extern "C" void kernel_launch(void* const* d_in, const int* in_sizes, int n_in,
                              void* d_out, int out_size) {
    const float* z      = (const float*)d_in[0];
    const float* emb    = (const float*)d_in[1];
    const float* l2h_w  = (const float*)d_in[2];
    const float* l2h_b  = (const float*)d_in[3];
    const float* r0wih  = (const float*)d_in[4];
    const float* r0whh  = (const float*)d_in[5];
    const float* r0bih  = (const float*)d_in[6];
    const float* r0bhh  = (const float*)d_in[7];
    const float* r1wih  = (const float*)d_in[8];
    const float* r1whh  = (const float*)d_in[9];
    const float* r1bih  = (const float*)d_in[10];
    const float* r1bhh  = (const float*)d_in[11];
    const float* head_w = (const float*)d_in[12];
    const float* tp0    = (const float*)d_in[13];
    const float* tw0    = (const float*)d_in[14];
    const float* tp1    = (const float*)d_in[15];
    const float* tw1    = (const float*)d_in[16];
    const float* tp2    = (const float*)d_in[17];
    const float* tw2    = (const float*)d_in[18];
    const int*   inp    = (const int*)d_in[19];
    const int*   target = (const int*)d_in[20];
    const int*   length = (const int*)d_in[21];
    float* out = (float*)d_out;

    __nv_bfloat16* gh1b = nullptr; __nv_bfloat16* gh2b = nullptr;
    __nv_bfloat16* ghidb = nullptr;
    float* gh2 = nullptr; float* gz = nullptr; float* gpw = nullptr;
    float* gpre = nullptr; float* glog = nullptr;
    cudaGetSymbolAddress((void**)&gh1b, g_h1b);
    cudaGetSymbolAddress((void**)&gh2b, g_h2b);
    cudaGetSymbolAddress((void**)&gh2, g_h2);
    cudaGetSymbolAddress((void**)&gz, g_zero);
    cudaGetSymbolAddress((void**)&gpw, g_pw);
    cudaGetSymbolAddress((void**)&ghidb, g_hiddenb);
    cudaGetSymbolAddress((void**)&gpre, g_pre);
    cudaGetSymbolAddress((void**)&glog, g_logits);

    cudaFuncSetAttribute(k_rnn_fused, cudaFuncAttributeMaxDynamicSharedMemorySize, RNN_SMEM);

    k_preptok<<<1, 256>>>(length, inp);
    k_hidden<<<(2 * BB * HH) / 256, 256>>>(z, l2h_w, l2h_b);

    // layer 0 input pre-activations: emb[tok] @ W0ih^T + b0ih + b0hh
    k_sgemm<<<dim3(64, 16), 256>>>(emb, r0wih, r0bih, r0bhh, gpre, 512, HH, 1);
    // fused 2-layer recurrence (bf16 state, warp-local butterfly reduce)
    k_rnn_fused<<<NBLK, 256, RNN_SMEM>>>(r0whh, r1wih, r1whh, gpre,
                                         r1bih, r1bhh, ghidb, gh1b, gh2, gh2b);

    k_pack<<<64 * HH / 256, 256>>>(head_w, tp2);
    // packed head + tail2-proj logits: [8192 x 64]
    k_sgemm<<<dim3(64, 1), 256>>>(gh2, gpw, gz, gz, glog, HH, 64, 0);

    k_head<<<NROWS / 256, 256>>>();
    k_tail2<<<NROWS / 32, 128>>>(tw2, target);
    k_tail01<<<NROWS, 128>>>(tp0, tw0, tp1, tw1, target);
    k_final<<<NROWS / 256, 256>>>(target);
    k_sum<<<1, 256>>>(out);
    (void)in_sizes; (void)n_in; (void)out_size;
}